// round 5
// baseline (speedup 1.0000x reference)
#include <cuda_runtime.h>
#include <math.h>

// Problem constants (fixed by the reference).
#define DD   128
#define HH   8
#define BB   8
#define SS   4096
#define EPSF 1e-8f
#define TB   4            // tokens processed per block-iteration (register blocking)
#define RSTRIDE 129       // padded row stride for R in SMEM (conflict-free both ways)
#define NBLOCKS 444       // 3 blocks/SM * 148 SMs

// SMEM layout (floats):
//   Rs  : 128*129  = 16512
//   xs  : 128*TB   = 512     (token vectors, interleaved [j][t] for LDS.128 broadcast)
//   red : 16                 (per-warp reduce partials, 4 warps x TB)
//   nrm : TB                 (sum of squares per token)
//   alp : TB                 (sum |res| per token)
#define SMEM_FLOATS (128*RSTRIDE + 128*TB + 16 + TB + TB)

__device__ __forceinline__ float warp_sum(float v) {
#pragma unroll
    for (int o = 16; o; o >>= 1) v += __shfl_xor_sync(0xffffffffu, v, o);
    return v;
}

// Reduce vals[0..TB) across 128 threads -> out4[t] (broadcast via SMEM). Includes syncs.
__device__ __forceinline__ void block_reduce4(const float* vals, float* red, float* out4, int tid) {
    int warp = tid >> 5, lane = tid & 31;
#pragma unroll
    for (int t = 0; t < TB; t++) {
        float s = warp_sum(vals[t]);
        if (lane == 0) red[warp * TB + t] = s;
    }
    __syncthreads();
    if (tid < TB) {
        out4[tid] = red[0 * TB + tid] + red[1 * TB + tid] + red[2 * TB + tid] + red[3 * TB + tid];
    }
    __syncthreads();
}

// ---------------- Phase 1: anchor head (ResidualQuant) ----------------
__global__ void __launch_bounds__(128, 3)
anchor_kernel(const float* __restrict__ kv, const float* __restrict__ Ra,
              const float* __restrict__ cba, float* __restrict__ out, int niter) {
    extern __shared__ float sm[];
    float* Rs  = sm;
    float* xs  = sm + 128 * RSTRIDE;
    float* red = xs + 128 * TB;
    float* nrm = red + 16;
    float* alp = nrm + TB;

    const int tid = threadIdx.x;

    // Stage R_anchor (row-major, padded stride 129).
#pragma unroll 8
    for (int k = 0; k < 128; k++) Rs[k * RSTRIDE + tid] = Ra[k * 128 + tid];

    const float c0 = cba[0], c1 = cba[1], c2 = cba[2], c3 = cba[3];
    const float t0 = 0.5f * (c0 + c1), t1 = 0.5f * (c1 + c2), t2 = 0.5f * (c2 + c3);
    __syncthreads();

    const float4* xs4 = (const float4*)xs;

    for (int it = blockIdx.x; it < niter; it += gridDim.x) {
        const int base = it * TB;  // token index base, token = b*SS + s

        float sq[TB];
#pragma unroll
        for (int t = 0; t < TB; t++) {
            int tok = base + t;
            int b = tok >> 12, s = tok & (SS - 1);
            float x = kv[((size_t)b * HH * SS + s) * DD + tid];
            sq[t] = x * x;
            xs[tid * TB + t] = x;
        }
        block_reduce4(sq, red, nrm, tid);  // nrm[t] = sum x^2 (xs visible after sync)

        // matvec1: u_i = sum_j R[i,j] * x_j   (i = tid)
        float acc[TB];
#pragma unroll
        for (int t = 0; t < TB; t++) acc[t] = 0.f;
#pragma unroll 8
        for (int j = 0; j < 128; j++) {
            float r = Rs[tid * RSTRIDE + j];
            float4 xv = xs4[j];
            acc[0] += r * xv.x; acc[1] += r * xv.y;
            acc[2] += r * xv.z; acc[3] += r * xv.w;
        }

        // Normalize + Lloyd-Max 4-level quantize + residual stats.
        float nn[TB], q0[TB], sg[TB], ares[TB];
#pragma unroll
        for (int t = 0; t < TB; t++) {
            nn[t] = sqrtf(nrm[t]);
            float y = acc[t] * (1.0f / (nn[t] + EPSF));
            float q = (y <= t1) ? ((y <= t0) ? c0 : c1) : ((y <= t2) ? c2 : c3);
            float res = y - q;
            q0[t] = q;
            sg[t] = (res > 0.f) ? 1.f : ((res < 0.f) ? -1.f : 0.f);
            ares[t] = fabsf(res);
        }
        block_reduce4(ares, red, alp, tid);  // sync inside also fences matvec1 reads of xs

        // y_hat = q0 + alpha * sign(res); stage into xs for matvec2.
#pragma unroll
        for (int t = 0; t < TB; t++) {
            float alpha = alp[t] * (1.0f / 128.0f);
            xs[tid * TB + t] = q0[t] + alpha * sg[t];
        }
        __syncthreads();

        // matvec2: rec_j = sum_i yhat_i * R[i,j]   (j = tid)
        float acc2[TB];
#pragma unroll
        for (int t = 0; t < TB; t++) acc2[t] = 0.f;
#pragma unroll 8
        for (int i = 0; i < 128; i++) {
            float r = Rs[i * RSTRIDE + tid];
            float4 yv = xs4[i];
            acc2[0] += r * yv.x; acc2[1] += r * yv.y;
            acc2[2] += r * yv.z; acc2[3] += r * yv.w;
        }
#pragma unroll
        for (int t = 0; t < TB; t++) {
            int tok = base + t;
            int b = tok >> 12, s = tok & (SS - 1);
            out[((size_t)b * HH * SS + s) * DD + tid] = acc2[t] * nn[t];
        }
        __syncthreads();  // protect xs/nrm before next iteration overwrites
    }
}

// ---------------- Phase 2: delta heads (PolarQuant vs anchor recon) ----------------
__global__ void __launch_bounds__(128, 3)
delta_kernel(const float* __restrict__ kv, const float* __restrict__ Rd,
             const float* __restrict__ cbd, float* __restrict__ out, int niter) {
    extern __shared__ float sm[];
    float* Rs  = sm;
    float* xs  = sm + 128 * RSTRIDE;
    float* red = xs + 128 * TB;
    float* nrm = red + 16;

    const int tid = threadIdx.x;

#pragma unroll 8
    for (int k = 0; k < 128; k++) Rs[k * RSTRIDE + tid] = Rd[k * 128 + tid];

    const float c0 = cbd[0], c1 = cbd[1];
    const float mid = 0.5f * (c0 + c1);
    __syncthreads();

    const float4* xs4 = (const float4*)xs;

    for (int it = blockIdx.x; it < niter; it += gridDim.x) {
        const int base = it * TB;  // token-head index: u = (b*(HH-1) + (h-1))*SS + s

        float av[TB], sq[TB];
        size_t ooff[TB];
#pragma unroll
        for (int t = 0; t < TB; t++) {
            int u = base + t;
            int b = u / ((HH - 1) * SS);
            int rem = u - b * ((HH - 1) * SS);
            int h = (rem >> 12) + 1;            // actual head 1..7
            int s = rem & (SS - 1);
            size_t kvo = ((size_t)(b * HH + h) * SS + s) * DD;
            size_t ao  = ((size_t)b * HH * SS + s) * DD;   // anchor recon lives in out head 0
            float a = out[ao + tid];
            float x = kv[kvo + tid] - a;
            av[t] = a;
            ooff[t] = kvo;                       // out offset == kv offset for this head
            sq[t] = x * x;
            xs[tid * TB + t] = x;
        }
        block_reduce4(sq, red, nrm, tid);

        // matvec1: u_i = sum_j Rd[i,j] * delta_j
        float acc[TB];
#pragma unroll
        for (int t = 0; t < TB; t++) acc[t] = 0.f;
#pragma unroll 8
        for (int j = 0; j < 128; j++) {
            float r = Rs[tid * RSTRIDE + j];
            float4 xv = xs4[j];
            acc[0] += r * xv.x; acc[1] += r * xv.y;
            acc[2] += r * xv.z; acc[3] += r * xv.w;
        }

        // 1-bit polar quantize (nearest of {c0,c1}; tie -> lower index).
        float nn[TB], qv[TB];
#pragma unroll
        for (int t = 0; t < TB; t++) {
            nn[t] = sqrtf(nrm[t]);
            float y = acc[t] * (1.0f / (nn[t] + EPSF));
            qv[t] = (y <= mid) ? c0 : c1;
        }
        __syncthreads();            // all matvec1 reads of xs done
#pragma unroll
        for (int t = 0; t < TB; t++) xs[tid * TB + t] = qv[t];
        __syncthreads();

        // matvec2: rec_j = sum_i q_i * Rd[i,j]
        float acc2[TB];
#pragma unroll
        for (int t = 0; t < TB; t++) acc2[t] = 0.f;
#pragma unroll 8
        for (int i = 0; i < 128; i++) {
            float r = Rs[i * RSTRIDE + tid];
            float4 yv = xs4[i];
            acc2[0] += r * yv.x; acc2[1] += r * yv.y;
            acc2[2] += r * yv.z; acc2[3] += r * yv.w;
        }
#pragma unroll
        for (int t = 0; t < TB; t++) {
            out[ooff[t] + tid] = av[t] + acc2[t] * nn[t];
        }
        __syncthreads();
    }
}

extern "C" void kernel_launch(void* const* d_in, const int* in_sizes, int n_in,
                              void* d_out, int out_size) {
    const float* kv  = (const float*)d_in[0];
    const float* Ra  = (const float*)d_in[1];
    const float* cba = (const float*)d_in[2];
    const float* Rd  = (const float*)d_in[3];
    const float* cbd = (const float*)d_in[4];
    float* out = (float*)d_out;

    const int smem_bytes = SMEM_FLOATS * (int)sizeof(float);
    cudaFuncSetAttribute(anchor_kernel, cudaFuncAttributeMaxDynamicSharedMemorySize, smem_bytes);
    cudaFuncSetAttribute(delta_kernel,  cudaFuncAttributeMaxDynamicSharedMemorySize, smem_bytes);

    const int n_anchor_iter = (BB * SS) / TB;             // 8192
    const int n_delta_iter  = (BB * (HH - 1) * SS) / TB;  // 57344

    anchor_kernel<<<NBLOCKS, 128, smem_bytes>>>(kv, Ra, cba, out, n_anchor_iter);
    delta_kernel <<<NBLOCKS, 128, smem_bytes>>>(kv, Rd, cbd, out, n_delta_iter);
}

// round 6
// speedup vs baseline: 1.9977x; 1.9977x over previous
#include <cuda_runtime.h>
#include <math.h>

// Problem constants (fixed by the reference).
#define DD   128
#define HH   8
#define BB   8
#define SS   4096
#define EPSF 1e-8f
#define TB   8            // tokens per warp-task
#define RSTRIDE 129       // padded R row stride: bank (L+j)%32 conflict-free both orientations
#define XSTRIDE 12        // xs row stride (floats): 48B rows -> 16B aligned, 4-way store conflicts only
#define WPB  8            // warps per block
#define NTHREAD 256
#define NBLOCK  296       // 2 blocks/SM * 148 SMs (one full wave)

#define SMEM_FLOATS (128*RSTRIDE + WPB*128*XSTRIDE)

// ---------------- Blackwell packed-fp32 helpers ----------------
__device__ __forceinline__ unsigned long long pack2(float x) {
    unsigned long long d; unsigned int u = __float_as_uint(x);
    asm("mov.b64 %0, {%1, %1};" : "=l"(d) : "r"(u));
    return d;
}
__device__ __forceinline__ void fma2(unsigned long long& d, unsigned long long a, unsigned long long b) {
    asm("fma.rn.f32x2 %0, %1, %2, %0;" : "+l"(d) : "l"(a), "l"(b));
}
__device__ __forceinline__ float2 unpack2(unsigned long long p) {
    unsigned int lo, hi;
    asm("mov.b64 {%0, %1}, %2;" : "=r"(lo), "=r"(hi) : "l"(p));
    return make_float2(__uint_as_float(lo), __uint_as_float(hi));
}
__device__ __forceinline__ float warp_sum(float v) {
#pragma unroll
    for (int o = 16; o; o >>= 1) v += __shfl_xor_sync(0xffffffffu, v, o);
    return v;
}

// Generic 128-long matvec accumulating 4 rows/cols x 8 tokens into 16 packed accumulators.
// acc[k*4+p] holds the (token 2p, 2p+1) pair for the lane's k-th output element.
// RSTEP=1: row mode (rk = base_k[j]); RSTEP=RSTRIDE: column mode.
template <int RSTEP>
__device__ __forceinline__ void matvec128(const float* __restrict__ r0, const float* __restrict__ r1,
                                          const float* __restrict__ r2, const float* __restrict__ r3,
                                          const float* __restrict__ xs, unsigned long long acc[16]) {
#pragma unroll
    for (int p = 0; p < 16; p++) acc[p] = 0ull;
#pragma unroll 8
    for (int j = 0; j < 128; j++) {
        unsigned long long rr0 = pack2(r0[j * RSTEP]);
        unsigned long long rr1 = pack2(r1[j * RSTEP]);
        unsigned long long rr2 = pack2(r2[j * RSTEP]);
        unsigned long long rr3 = pack2(r3[j * RSTEP]);
        // broadcast LDS.128 x2: tokens 0..3 and 4..7 for this j
        ulonglong2 pa = *(const ulonglong2*)(xs + j * XSTRIDE);
        ulonglong2 pb = *(const ulonglong2*)(xs + j * XSTRIDE + 4);
        fma2(acc[0],  rr0, pa.x); fma2(acc[1],  rr0, pa.y); fma2(acc[2],  rr0, pb.x); fma2(acc[3],  rr0, pb.y);
        fma2(acc[4],  rr1, pa.x); fma2(acc[5],  rr1, pa.y); fma2(acc[6],  rr1, pb.x); fma2(acc[7],  rr1, pb.y);
        fma2(acc[8],  rr2, pa.x); fma2(acc[9],  rr2, pa.y); fma2(acc[10], rr2, pb.x); fma2(acc[11], rr2, pb.y);
        fma2(acc[12], rr3, pa.x); fma2(acc[13], rr3, pa.y); fma2(acc[14], rr3, pb.x); fma2(acc[15], rr3, pb.y);
    }
}

// Stage R (row-major, padded stride) cooperatively with all 256 threads.
__device__ __forceinline__ void stage_R(float* Rs, const float* __restrict__ R, int tid) {
#pragma unroll 4
    for (int idx = tid; idx < 128 * 128; idx += NTHREAD) {
        int i = idx >> 7, j = idx & 127;
        Rs[i * RSTRIDE + j] = R[idx];
    }
}

// ---------------- Phase 1: anchor head (ResidualQuant) ----------------
__global__ void __launch_bounds__(NTHREAD, 2)
anchor_kernel(const float* __restrict__ kv, const float* __restrict__ Ra,
              const float* __restrict__ cba, float* __restrict__ out, int ntask) {
    extern __shared__ float sm[];
    float* Rs = sm;
    const int tid = threadIdx.x;
    const int w = tid >> 5, L = tid & 31;
    float* xs = sm + 128 * RSTRIDE + w * (128 * XSTRIDE);

    stage_R(Rs, Ra, tid);
    const float c0 = cba[0], c1 = cba[1], c2 = cba[2], c3 = cba[3];
    const float t0 = 0.5f * (c0 + c1), t1 = 0.5f * (c1 + c2), t2 = 0.5f * (c2 + c3);
    __syncthreads();

    // per-lane R access pointers (bank-conflict-free: bank = (L + j) % 32)
    const float* rr0 = Rs + (L +  0) * RSTRIDE;   // rows for matvec1
    const float* rr1 = Rs + (L + 32) * RSTRIDE;
    const float* rr2 = Rs + (L + 64) * RSTRIDE;
    const float* rr3 = Rs + (L + 96) * RSTRIDE;
    const float* rc0 = Rs + (L +  0);             // cols for matvec2
    const float* rc1 = Rs + (L + 32);
    const float* rc2 = Rs + (L + 64);
    const float* rc3 = Rs + (L + 96);

    for (int task = blockIdx.x * WPB + w; task < ntask; task += gridDim.x * WPB) {
        const int base = task * TB;   // anchor token index = b*SS + s
        unsigned int kvo[TB];
        float nn[TB], inv[TB];

        // ---- stage x into xs[j][t], accumulate sum(x^2) per token ----
#pragma unroll
        for (int t = 0; t < TB; t++) {
            int tok = base + t;
            int b = tok >> 12, s = tok & (SS - 1);
            unsigned int o = ((unsigned)(b * HH) * SS + (unsigned)s) * DD;
            kvo[t] = o;
            float ssq = 0.f;
#pragma unroll
            for (int c = 0; c < 4; c++) {
                int j = L + 32 * c;
                float x = kv[o + j];
                xs[j * XSTRIDE + t] = x;
                ssq += x * x;
            }
            float tot = warp_sum(ssq);
            nn[t] = sqrtf(tot);
            inv[t] = 1.0f / (nn[t] + EPSF);
        }
        __syncwarp();

        // ---- matvec1: y_i = sum_j R[i,j] x_j ----
        unsigned long long acc[16];
        matvec128<1>(rr0, rr1, rr2, rr3, xs, acc);

        // ---- pass A: quantize + accumulate |res| per token ----
        float ares[TB];
#pragma unroll
        for (int t = 0; t < TB; t++) ares[t] = 0.f;
#pragma unroll
        for (int k = 0; k < 4; k++) {
#pragma unroll
            for (int p = 0; p < 4; p++) {
                float2 y = unpack2(acc[k * 4 + p]);
                float y0 = y.x * inv[2 * p], y1 = y.y * inv[2 * p + 1];
                float q0 = (y0 <= t1) ? ((y0 <= t0) ? c0 : c1) : ((y0 <= t2) ? c2 : c3);
                float q1 = (y1 <= t1) ? ((y1 <= t0) ? c0 : c1) : ((y1 <= t2) ? c2 : c3);
                ares[2 * p]     += fabsf(y0 - q0);
                ares[2 * p + 1] += fabsf(y1 - q1);
            }
        }
        float alpha[TB];
#pragma unroll
        for (int t = 0; t < TB; t++) alpha[t] = warp_sum(ares[t]) * (1.0f / 128.0f);

        __syncwarp();   // matvec1 finished reading xs everywhere in this warp

        // ---- pass B: yhat = q0 + alpha*sign(res), store to xs ----
#pragma unroll
        for (int k = 0; k < 4; k++) {
            int i = L + 32 * k;
#pragma unroll
            for (int p = 0; p < 4; p++) {
                float2 y = unpack2(acc[k * 4 + p]);
#pragma unroll
                for (int h = 0; h < 2; h++) {
                    int t = 2 * p + h;
                    float yy = (h ? y.y : y.x) * inv[t];
                    float q = (yy <= t1) ? ((yy <= t0) ? c0 : c1) : ((yy <= t2) ? c2 : c3);
                    float res = yy - q;
                    float sg = (res > 0.f) ? 1.f : ((res < 0.f) ? -1.f : 0.f);
                    xs[i * XSTRIDE + t] = q + alpha[t] * sg;
                }
            }
        }
        __syncwarp();

        // ---- matvec2: rec_j = sum_i yhat_i R[i,j] ----
        matvec128<RSTRIDE>(rc0, rc1, rc2, rc3, xs, acc);

        // ---- output: out = rec * norm ----
#pragma unroll
        for (int k = 0; k < 4; k++) {
            int j = L + 32 * k;
#pragma unroll
            for (int p = 0; p < 4; p++) {
                float2 r = unpack2(acc[k * 4 + p]);
                out[kvo[2 * p]     + j] = r.x * nn[2 * p];
                out[kvo[2 * p + 1] + j] = r.y * nn[2 * p + 1];
            }
        }
        __syncwarp();   // protect xs before next task restages
    }
}

// ---------------- Phase 2: delta heads (PolarQuant vs anchor recon) ----------------
__global__ void __launch_bounds__(NTHREAD, 2)
delta_kernel(const float* __restrict__ kv, const float* __restrict__ Rd,
             const float* __restrict__ cbd, float* __restrict__ out, int ntask) {
    extern __shared__ float sm[];
    float* Rs = sm;
    const int tid = threadIdx.x;
    const int w = tid >> 5, L = tid & 31;
    float* xs = sm + 128 * RSTRIDE + w * (128 * XSTRIDE);

    stage_R(Rs, Rd, tid);
    const float c0 = cbd[0], c1 = cbd[1];
    const float mid = 0.5f * (c0 + c1);
    __syncthreads();

    const float* rr0 = Rs + (L +  0) * RSTRIDE;
    const float* rr1 = Rs + (L + 32) * RSTRIDE;
    const float* rr2 = Rs + (L + 64) * RSTRIDE;
    const float* rr3 = Rs + (L + 96) * RSTRIDE;
    const float* rc0 = Rs + (L +  0);
    const float* rc1 = Rs + (L + 32);
    const float* rc2 = Rs + (L + 64);
    const float* rc3 = Rs + (L + 96);

    for (int task = blockIdx.x * WPB + w; task < ntask; task += gridDim.x * WPB) {
        const int base = task * TB;   // token-head index u = (b*(HH-1)+(h-1))*SS + s
        unsigned int kvo[TB], ao[TB];
        float nn[TB], inv[TB];

        // ---- stage delta = kv - anchor_recon; sum of squares ----
#pragma unroll
        for (int t = 0; t < TB; t++) {
            int u = base + t;
            int b = u / ((HH - 1) * SS);
            int rem = u - b * ((HH - 1) * SS);
            int h = (rem >> 12) + 1;
            int s = rem & (SS - 1);
            unsigned int ko = ((unsigned)(b * HH + h) * SS + (unsigned)s) * DD;
            unsigned int aoo = ((unsigned)(b * HH) * SS + (unsigned)s) * DD;  // anchor recon: out head 0
            kvo[t] = ko; ao[t] = aoo;
            float ssq = 0.f;
#pragma unroll
            for (int c = 0; c < 4; c++) {
                int j = L + 32 * c;
                float x = kv[ko + j] - out[aoo + j];
                xs[j * XSTRIDE + t] = x;
                ssq += x * x;
            }
            float tot = warp_sum(ssq);
            nn[t] = sqrtf(tot);
            inv[t] = 1.0f / (nn[t] + EPSF);
        }
        __syncwarp();

        // ---- matvec1 ----
        unsigned long long acc[16];
        matvec128<1>(rr0, rr1, rr2, rr3, xs, acc);

        __syncwarp();   // all lanes done reading xs

        // ---- 1-bit polar quantize, store to xs ----
#pragma unroll
        for (int k = 0; k < 4; k++) {
            int i = L + 32 * k;
#pragma unroll
            for (int p = 0; p < 4; p++) {
                float2 y = unpack2(acc[k * 4 + p]);
                float y0 = y.x * inv[2 * p], y1 = y.y * inv[2 * p + 1];
                xs[i * XSTRIDE + 2 * p]     = (y0 <= mid) ? c0 : c1;
                xs[i * XSTRIDE + 2 * p + 1] = (y1 <= mid) ? c0 : c1;
            }
        }
        __syncwarp();

        // ---- matvec2 ----
        matvec128<RSTRIDE>(rc0, rc1, rc2, rc3, xs, acc);

        // ---- output: out = anchor + rec * norm (reload anchor; L1/L2 hit) ----
#pragma unroll
        for (int k = 0; k < 4; k++) {
            int j = L + 32 * k;
#pragma unroll
            for (int p = 0; p < 4; p++) {
                float2 r = unpack2(acc[k * 4 + p]);
                int ta = 2 * p, tb = 2 * p + 1;
                out[kvo[ta] + j] = out[ao[ta] + j] + r.x * nn[ta];
                out[kvo[tb] + j] = out[ao[tb] + j] + r.y * nn[tb];
            }
        }
        __syncwarp();
    }
}

extern "C" void kernel_launch(void* const* d_in, const int* in_sizes, int n_in,
                              void* d_out, int out_size) {
    const float* kv  = (const float*)d_in[0];
    const float* Ra  = (const float*)d_in[1];
    const float* cba = (const float*)d_in[2];
    const float* Rd  = (const float*)d_in[3];
    const float* cbd = (const float*)d_in[4];
    float* out = (float*)d_out;

    const int smem_bytes = SMEM_FLOATS * (int)sizeof(float);  // 115200
    cudaFuncSetAttribute(anchor_kernel, cudaFuncAttributeMaxDynamicSharedMemorySize, smem_bytes);
    cudaFuncSetAttribute(delta_kernel,  cudaFuncAttributeMaxDynamicSharedMemorySize, smem_bytes);

    const int n_anchor_task = (BB * SS) / TB;             // 4096
    const int n_delta_task  = (BB * (HH - 1) * SS) / TB;  // 28672

    anchor_kernel<<<NBLOCK, NTHREAD, smem_bytes>>>(kv, Ra, cba, out, n_anchor_task);
    delta_kernel <<<NBLOCK, NTHREAD, smem_bytes>>>(kv, Rd, cbd, out, n_delta_task);
}